// round 4
// baseline (speedup 1.0000x reference)
#include <cuda_runtime.h>

#define BB 8
#define CC 512
#define TT 8192
#define OPT 8               // outputs per thread
#define NT 256              // threads per block
#define CHUNK (NT * OPT)    // 2048 outputs per block
#define NCHUNK (TT / CHUNK) // 4 blocks per (b,c) row
#define SZ 1283             // padded u64 slots per z array (P=0..1026 -> idx max 1282)

typedef unsigned long long u64;

__device__ __forceinline__ u64 pk2(float lo, float hi) {
    u64 r; asm("mov.b64 %0, {%1, %2};" : "=l"(r) : "f"(lo), "f"(hi)); return r;
}
__device__ __forceinline__ void upk2(u64 v, float& lo, float& hi) {
    asm("mov.b64 {%0, %1}, %2;" : "=f"(lo), "=f"(hi) : "l"(v));
}
__device__ __forceinline__ float lo32(u64 v) { float l, h; upk2(v, l, h); return l; }
__device__ __forceinline__ float hi32(u64 v) { float l, h; upk2(v, l, h); return h; }
__device__ __forceinline__ u64 fma2(u64 a, u64 b, u64 c) {
    u64 d; asm("fma.rn.f32x2 %0, %1, %2, %3;" : "=l"(d) : "l"(a), "l"(b), "l"(c)); return d;
}
__device__ __forceinline__ u64 mul2(u64 a, u64 b) {
    u64 d; asm("mul.rn.f32x2 %0, %1, %2;" : "=l"(d) : "l"(a), "l"(b)); return d;
}

__global__ __launch_bounds__(NT) void aa_fused_kernel(
    const float* __restrict__ x,
    const float* __restrict__ alpha,
    const float* __restrict__ beta,
    const float* __restrict__ fu,
    const float* __restrict__ fd,
    float* __restrict__ out)
{
    // z pair arrays: s_zo[idx(P)] = (z_odd[K00+2P], z_odd[K00+2P+1]), K00 = ob-2.
    // idx(P) = P + (P>>2): one pad slot per 4 -> per-thread offsets are compile-time,
    // lane stride 10 words -> conflict-free half-warp wavefronts.
    __shared__ u64 s_zo[SZ], s_ze[SZ];
    __shared__ float s_g0[6], s_g1[6], s_fd[12];
    __shared__ float s_a, s_ib;

    const int tid = threadIdx.x;
    const int bid = blockIdx.x;
    const int row = bid >> 2;      // NCHUNK == 4
    const int chunk = bid & 3;
    const int c = row & (CC - 1);

    if (tid < 6)        s_g0[tid] = 2.0f * fu[10 - 2 * tid];                   // odd-n phase taps
    else if (tid < 12)  { int r = tid - 6; s_g1[r] = 2.0f * fu[11 - 2 * r]; }  // even-n phase taps
    else if (tid < 24)  s_fd[tid - 12] = fd[tid - 12];
    else if (tid == 24) s_a  = expf(alpha[c]);
    else if (tid == 25) s_ib = 1.0f / (expf(beta[c]) + 1e-9f);
    __syncthreads();

    const float a  = s_a;
    const float ib = s_ib;
    const u64 a2  = pk2(a, a);
    const u64 ib2 = pk2(ib, ib);

    const float* xrow = x + (size_t)row * TT;
    float* orow = out + (size_t)row * TT;
    const int ob = chunk * CHUNK;

    // snake, elementwise on a packed pair
    auto snake2 = [&](u64 y) -> u64 {
        float t0, t1; upk2(mul2(y, a2), t0, t1);
        u64 s2 = pk2(__sinf(t0), __sinf(t1));
        return fma2(mul2(s2, s2), ib2, y);
    };

    // scalar clamped z for edges/extras; n = upsampled index
    auto zval = [&](int n) -> float {
        n = min(max(n, 0), 2 * TT - 1);
        const int m = n >> 1;
        float acc = 0.0f;
        if (n & 1) {
            #pragma unroll
            for (int r = 0; r < 6; r++) {
                const int j = min(max(m - 2 + r, 0), TT - 1);
                acc += s_g0[r] * __ldg(&xrow[j]);
            }
        } else {
            #pragma unroll
            for (int r = 0; r < 6; r++) {
                const int j = min(max(m - 3 + r, 0), TT - 1);
                acc += s_g1[r] * __ldg(&xrow[j]);
            }
        }
        const float sv = __sinf(acc * a);
        return acc + sv * sv * ib;
    };

    // ---------------- Phase 1: each z computed once, natural packing ----------------
    {
        const int K0 = ob - 2 + 8 * tid;           // first pair index this thread owns
        const int xb = ob + 8 * tid - 8;           // x window base (float4-aligned, even)
        const bool fast = (xb >= 0) && (xb + 16 <= TT);
        if (fast) {
            u64 g0b[6], g1b[6];
            #pragma unroll
            for (int r = 0; r < 6; r++) { g0b[r] = pk2(s_g0[r], s_g0[r]); g1b[r] = pk2(s_g1[r], s_g1[r]); }

            float xl[16];
            const float4* xv = (const float4*)(xrow + xb);
            #pragma unroll
            for (int i = 0; i < 4; i++) {
                float4 v = xv[i];
                xl[4 * i + 0] = v.x; xl[4 * i + 1] = v.y;
                xl[4 * i + 2] = v.z; xl[4 * i + 3] = v.w;
            }
            u64 A[8], S[7];
            #pragma unroll
            for (int p = 0; p < 8; p++) A[p] = pk2(xl[2 * p], xl[2 * p + 1]);       // aligned pairs
            #pragma unroll
            for (int p = 1; p < 7; p++) S[p] = pk2(xl[2 * p + 1], xl[2 * p + 2]);   // shifted pairs

            #pragma unroll
            for (int i = 0; i < 4; i++) {
                // pair-of-pairs k = K0+2i: X_r base = 2i+3+r in xl
                const u64 X0 = S[i + 1], X1 = A[i + 2], X2 = S[i + 2];
                const u64 X3 = A[i + 3], X4 = S[i + 3], X5 = A[i + 4];
                u64 zo = mul2(g0b[0], X0);
                zo = fma2(g0b[1], X1, zo); zo = fma2(g0b[2], X2, zo);
                zo = fma2(g0b[3], X3, zo); zo = fma2(g0b[4], X4, zo);
                zo = fma2(g0b[5], X5, zo);
                u64 ze = mul2(g1b[0], X0);
                ze = fma2(g1b[1], X1, ze); ze = fma2(g1b[2], X2, ze);
                ze = fma2(g1b[3], X3, ze); ze = fma2(g1b[4], X4, ze);
                ze = fma2(g1b[5], X5, ze);
                s_zo[5 * tid + i] = snake2(zo);
                s_ze[5 * tid + i] = snake2(ze);
            }
        } else {
            // edge thread (t=0 of chunk 0 only)
            #pragma unroll
            for (int i = 0; i < 4; i++) {
                const int k = K0 + 2 * i;
                s_zo[5 * tid + i] = pk2(zval(2 * k - 1), zval(2 * k + 1));
                s_ze[5 * tid + i] = pk2(zval(2 * k),     zval(2 * k + 2));
            }
        }
        // extras: P = 1024..1026 (pairs k = ob+2046 .. ob+2051), clamped scalar path
        if (tid < 3) {
            const int P = 1024 + tid;
            const int k = (ob - 2) + 2 * P;
            const int idx = P + (P >> 2);
            s_zo[idx] = pk2(zval(2 * k - 1), zval(2 * k + 1));
            s_ze[idx] = pk2(zval(2 * k),     zval(2 * k + 2));
        }
    }
    __syncthreads();

    // ---------------- Phase 2: packed downsample from smem ----------------
    // zoP[j] starts at pair tb-2+2j; offsets idx(4t+j) = 5t + {0,1,2,3,5,6,7}
    u64 zoP[7], zeP[7];
    {
        const int b5 = 5 * tid;
        zoP[0] = s_zo[b5 + 0]; zoP[1] = s_zo[b5 + 1]; zoP[2] = s_zo[b5 + 2];
        zoP[3] = s_zo[b5 + 3]; zoP[4] = s_zo[b5 + 5]; zoP[5] = s_zo[b5 + 6];
        zoP[6] = s_zo[b5 + 7];
        zeP[0] = s_ze[b5 + 0]; zeP[1] = s_ze[b5 + 1]; zeP[2] = s_ze[b5 + 2];
        zeP[3] = s_ze[b5 + 3]; zeP[4] = s_ze[b5 + 5]; zeP[5] = s_ze[b5 + 6];
        zeP[6] = s_ze[b5 + 7];
    }
    u64 zoS[6], zeS[6];
    #pragma unroll
    for (int j = 0; j < 6; j++) {
        zoS[j] = pk2(hi32(zoP[j]), lo32(zoP[j + 1]));
        zeS[j] = pk2(hi32(zeP[j]), lo32(zeP[j + 1]));
    }

    u64 dO[6], dE[6];
    #pragma unroll
    for (int u = 0; u < 6; u++) {
        dO[u] = pk2(s_fd[2 * u],     s_fd[2 * u]);
        dE[u] = pk2(s_fd[2 * u + 1], s_fd[2 * u + 1]);
    }

    float o[OPT];
    #pragma unroll
    for (int cc2 = 0; cc2 < 4; cc2++) {
        // (out[m], out[m+1]), m = tb + 2*cc2
        u64 acc = mul2(dO[0], zoP[cc2]);
        acc = fma2(dE[0], zeP[cc2], acc);
        acc = fma2(dO[1], zoS[cc2], acc);
        acc = fma2(dE[1], zeS[cc2], acc);
        acc = fma2(dO[2], zoP[cc2 + 1], acc);
        acc = fma2(dE[2], zeP[cc2 + 1], acc);
        acc = fma2(dO[3], zoS[cc2 + 1], acc);
        acc = fma2(dE[3], zeS[cc2 + 1], acc);
        acc = fma2(dO[4], zoP[cc2 + 2], acc);
        acc = fma2(dE[4], zeP[cc2 + 2], acc);
        acc = fma2(dO[5], zoS[cc2 + 2], acc);
        acc = fma2(dE[5], zeS[cc2 + 2], acc);
        upk2(acc, o[2 * cc2], o[2 * cc2 + 1]);
    }
    float4* ov = (float4*)(orow + ob + 8 * tid);
    ov[0] = make_float4(o[0], o[1], o[2], o[3]);
    ov[1] = make_float4(o[4], o[5], o[6], o[7]);
}

extern "C" void kernel_launch(void* const* d_in, const int* in_sizes, int n_in,
                              void* d_out, int out_size)
{
    const float* x     = (const float*)d_in[0];
    const float* alpha = (const float*)d_in[1];
    const float* beta  = (const float*)d_in[2];
    const float* fu    = (const float*)d_in[3];
    const float* fd    = (const float*)d_in[4];
    float* out = (float*)d_out;

    const int grid = BB * CC * NCHUNK; // 16384
    aa_fused_kernel<<<grid, NT>>>(x, alpha, beta, fu, fd, out);
}